// round 3
// baseline (speedup 1.0000x reference)
#include <cuda_runtime.h>
#include <cuda_bf16.h>
#include <math.h>

// Problem constants
#define LAYERS 6
#define Hc 1024
#define NHc 16
#define Dc 64
#define Fc 4096
#define Bc 4
#define Sc 512
#define Mrows (Bc * Sc)          // 2048
#define LN_EPS 1e-12f
#define GELU_C 0.7978845608028654f

// ---------------------------------------------------------------------------
// Scratch buffers (device globals; no allocation allowed)
// ---------------------------------------------------------------------------
__device__ float g_h[Mrows * Hc];
__device__ float g_q[Mrows * Hc];
__device__ float g_k[Mrows * Hc];
__device__ float g_v[Mrows * Hc];
__device__ float g_a[Mrows * Hc];
__device__ float g_t[Mrows * Hc];
__device__ float g_x1[Mrows * Hc];
__device__ float g_x2[Mrows * Hc];
__device__ float g_x3[Mrows * Hc];
__device__ float g_inter[Mrows * Fc];

// ---------------------------------------------------------------------------
// GEMM: C[M,N] = A[M,K] @ W[K,N] + bias[N] (+ add[M,N]) (+ gelu)
// 64x64 block tile, BK=16, 256 threads, 4x4 per thread.
// Assumes M%64==0, N%64==0, K%16==0 (true for all calls here).
// ---------------------------------------------------------------------------
#define BM 64
#define BN 64
#define BK 16

__device__ __forceinline__ float gelu_new(float x) {
    return 0.5f * x * (1.0f + tanhf(GELU_C * (x + 0.044715f * x * x * x)));
}

__global__ __launch_bounds__(256) void gemm_kernel(
    const float* __restrict__ A, const float* __restrict__ W,
    const float* __restrict__ bias, const float* __restrict__ add,
    float* __restrict__ C, int M, int N, int K, int fuse_gelu)
{
    __shared__ float As[BM][BK + 1];
    __shared__ float Bs[BK][BN + 1];

    const int tid = threadIdx.x;
    const int bm = blockIdx.y * BM;
    const int bn = blockIdx.x * BN;
    const int tx = tid & 15;
    const int ty = tid >> 4;

    float acc[4][4] = {};

    for (int k0 = 0; k0 < K; k0 += BK) {
        // Load A tile: 64x16 = 1024 elems, 4 per thread
        #pragma unroll
        for (int l = 0; l < 4; l++) {
            int e = tid + 256 * l;
            int m = e >> 4, k = e & 15;
            As[m][k] = A[(bm + m) * K + k0 + k];
        }
        // Load W tile: 16x64
        #pragma unroll
        for (int l = 0; l < 4; l++) {
            int e = tid + 256 * l;
            int k = e >> 6, n = e & 63;
            Bs[k][n] = W[(k0 + k) * N + bn + n];
        }
        __syncthreads();

        #pragma unroll
        for (int k = 0; k < BK; k++) {
            float a[4], b[4];
            #pragma unroll
            for (int i = 0; i < 4; i++) a[i] = As[ty * 4 + i][k];
            #pragma unroll
            for (int j = 0; j < 4; j++) b[j] = Bs[k][tx * 4 + j];
            #pragma unroll
            for (int i = 0; i < 4; i++)
                #pragma unroll
                for (int j = 0; j < 4; j++)
                    acc[i][j] += a[i] * b[j];
        }
        __syncthreads();
    }

    #pragma unroll
    for (int i = 0; i < 4; i++) {
        int row = bm + ty * 4 + i;
        #pragma unroll
        for (int j = 0; j < 4; j++) {
            int col = bn + tx * 4 + j;
            float val = acc[i][j] + bias[col];
            if (add) val += add[row * N + col];
            if (fuse_gelu) val = gelu_new(val);
            C[row * N + col] = val;
        }
    }
}

// ---------------------------------------------------------------------------
// Attention: out = softmax(Q K^T * scale + maskadd) V  for all heads.
// Q,K,V are [B, S, H] with heads interleaved (h = n*D + d).
// One block handles QT=8 query rows for one (b, head). 256 threads.
// ---------------------------------------------------------------------------
#define QT 8

__global__ __launch_bounds__(256) void attn_kernel(
    const float* __restrict__ Q, const float* __restrict__ Kk,
    const float* __restrict__ V, const int* __restrict__ mask,
    float* __restrict__ O, int Sq, int Skv)
{
    __shared__ float qs[QT][Dc];
    __shared__ float p[QT][Sc];   // Skv <= Sc

    const int tid = threadIdx.x;
    const int nqt = Sq / QT;
    const int qt = blockIdx.x % nqt;
    const int n  = (blockIdx.x / nqt) % NHc;
    const int b  = blockIdx.x / (nqt * NHc);
    const int i0 = qt * QT;

    // Load Q tile [QT][D]
    for (int e = tid; e < QT * Dc; e += 256) {
        int r = e / Dc, d = e % Dc;
        qs[r][d] = Q[(b * Sq + i0 + r) * Hc + n * Dc + d];
    }
    __syncthreads();

    // Scores: each thread owns key columns j = tid, tid+256
    for (int j = tid; j < Skv; j += 256) {
        const float* kp = Kk + (b * Skv + j) * Hc + n * Dc;
        float acc[QT];
        #pragma unroll
        for (int r = 0; r < QT; r++) acc[r] = 0.f;
        #pragma unroll 16
        for (int d = 0; d < Dc; d++) {
            float kd = kp[d];
            #pragma unroll
            for (int r = 0; r < QT; r++) acc[r] += qs[r][d] * kd;
        }
        float madd = mask[b * Skv + j] ? 0.f : -10000.f;
        #pragma unroll
        for (int r = 0; r < QT; r++) p[r][j] = acc[r] * 0.125f + madd;
    }
    __syncthreads();

    // Softmax: warp w handles row w (8 warps, 8 rows)
    {
        int w = tid >> 5, lane = tid & 31;
        float m = -1e30f;
        for (int j = lane; j < Skv; j += 32) m = fmaxf(m, p[w][j]);
        #pragma unroll
        for (int o = 16; o > 0; o >>= 1) m = fmaxf(m, __shfl_xor_sync(0xffffffffu, m, o));
        float s = 0.f;
        for (int j = lane; j < Skv; j += 32) {
            float e = __expf(p[w][j] - m);
            p[w][j] = e;
            s += e;
        }
        #pragma unroll
        for (int o = 16; o > 0; o >>= 1) s += __shfl_xor_sync(0xffffffffu, s, o);
        float inv = 1.f / s;
        for (int j = lane; j < Skv; j += 32) p[w][j] *= inv;
    }
    __syncthreads();

    // Output: group g = tid/64 handles rows {2g, 2g+1}, lane dim d = tid%64
    const int d = tid & 63;
    const int r0 = (tid >> 6) * 2;
    float a0 = 0.f, a1 = 0.f;
    for (int j = 0; j < Skv; j++) {
        float vd = V[(b * Skv + j) * Hc + n * Dc + d];
        a0 += p[r0][j] * vd;
        a1 += p[r0 + 1][j] * vd;
    }
    O[(b * Sq + i0 + r0) * Hc + n * Dc + d]     = a0;
    O[(b * Sq + i0 + r0 + 1) * Hc + n * Dc + d] = a1;
}

// ---------------------------------------------------------------------------
// LayerNorm over H=1024: one block (256 threads) per row.
// ln points at [2, H]: gamma = ln[0:H], beta = ln[H:2H].
// ---------------------------------------------------------------------------
__device__ __forceinline__ float block_sum_256(float v) {
    __shared__ float sh[8];
    #pragma unroll
    for (int o = 16; o > 0; o >>= 1) v += __shfl_xor_sync(0xffffffffu, v, o);
    __syncthreads();
    if ((threadIdx.x & 31) == 0) sh[threadIdx.x >> 5] = v;
    __syncthreads();
    float t = sh[0];
    #pragma unroll
    for (int i = 1; i < 8; i++) t += sh[i];
    return t;
}

__global__ __launch_bounds__(256) void ln_kernel(
    const float* __restrict__ x, const float* __restrict__ ln,
    float* __restrict__ out)
{
    const int row = blockIdx.x, tid = threadIdx.x;
    const float* xr = x + row * Hc;
    float v[4];
    float s = 0.f;
    #pragma unroll
    for (int i = 0; i < 4; i++) { v[i] = xr[tid + 256 * i]; s += v[i]; }
    s = block_sum_256(s);
    const float mean = s * (1.f / Hc);
    float q = 0.f;
    #pragma unroll
    for (int i = 0; i < 4; i++) { float d = v[i] - mean; q += d * d; }
    q = block_sum_256(q);
    const float inv = rsqrtf(q * (1.f / Hc) + LN_EPS);
    #pragma unroll
    for (int i = 0; i < 4; i++) {
        int c = tid + 256 * i;
        out[row * Hc + c] = (v[i] - mean) * inv * ln[c] + ln[Hc + c];
    }
}

// ---------------------------------------------------------------------------
// Orchestration
// ---------------------------------------------------------------------------
extern "C" void kernel_launch(void* const* d_in, const int* in_sizes, int n_in,
                              void* d_out, int out_size)
{
    const float* hidden   = (const float*)d_in[0];
    const float* enc      = (const float*)d_in[1];
    const int*   amask    = (const int*)d_in[2];
    const int*   emask    = (const int*)d_in[3];
    const float* sa_qkv_w = (const float*)d_in[4];
    const float* sa_qkv_b = (const float*)d_in[5];
    const float* sa_out_w = (const float*)d_in[6];
    const float* sa_out_b = (const float*)d_in[7];
    const float* sa_ln    = (const float*)d_in[8];
    const float* ca_qkv_w = (const float*)d_in[9];
    const float* ca_qkv_b = (const float*)d_in[10];
    const float* ca_out_w = (const float*)d_in[11];
    const float* ca_out_b = (const float*)d_in[12];
    const float* ca_ln    = (const float*)d_in[13];
    const float* o1_w     = (const float*)d_in[14];
    const float* o1_b     = (const float*)d_in[15];
    const float* o1_ln    = (const float*)d_in[16];
    const float* ffn_w    = (const float*)d_in[17];
    const float* ffn_b    = (const float*)d_in[18];
    const float* o2_w     = (const float*)d_in[19];
    const float* o2_b     = (const float*)d_in[20];
    const float* o2_ln    = (const float*)d_in[21];
    float* out = (float*)d_out;

    float *h, *q, *k, *v, *a, *t, *x1, *x2, *x3, *inter;
    cudaGetSymbolAddress((void**)&h,  g_h);
    cudaGetSymbolAddress((void**)&q,  g_q);
    cudaGetSymbolAddress((void**)&k,  g_k);
    cudaGetSymbolAddress((void**)&v,  g_v);
    cudaGetSymbolAddress((void**)&a,  g_a);
    cudaGetSymbolAddress((void**)&t,  g_t);
    cudaGetSymbolAddress((void**)&x1, g_x1);
    cudaGetSymbolAddress((void**)&x2, g_x2);
    cudaGetSymbolAddress((void**)&x3, g_x3);
    cudaGetSymbolAddress((void**)&inter, g_inter);

    cudaMemcpyAsync(h, hidden, (size_t)Mrows * Hc * sizeof(float),
                    cudaMemcpyDeviceToDevice, 0);

    const dim3 g1(Hc / BN, Mrows / BM);    // N=1024 GEMMs
    const dim3 gF(Fc / BN, Mrows / BM);    // N=4096 GEMM
    const int attnBlocks = Bc * NHc * (Sc / QT);   // 4096

    for (int i = 0; i < LAYERS; i++) {
        // ---- self attention ----
        const float* W  = sa_qkv_w + (size_t)i * 3 * Hc * Hc;
        const float* Bb = sa_qkv_b + (size_t)i * 3 * Hc;
        gemm_kernel<<<g1, 256>>>(h, W,                 Bb,          nullptr, q, Mrows, Hc, Hc, 0);
        gemm_kernel<<<g1, 256>>>(h, W + Hc * Hc,       Bb + Hc,     nullptr, k, Mrows, Hc, Hc, 0);
        gemm_kernel<<<g1, 256>>>(h, W + 2 * Hc * Hc,   Bb + 2 * Hc, nullptr, v, Mrows, Hc, Hc, 0);
        attn_kernel<<<attnBlocks, 256>>>(q, k, v, amask, a, Sc, Sc);
        gemm_kernel<<<g1, 256>>>(a, sa_out_w + (size_t)i * Hc * Hc, sa_out_b + i * Hc, h, t,
                                 Mrows, Hc, Hc, 0);
        ln_kernel<<<Mrows, 256>>>(t, sa_ln + (size_t)i * 2 * Hc, x1);

        // ---- cross attention (queries from h, keys/values from encoder) ----
        const float* Wc  = ca_qkv_w + (size_t)i * 3 * Hc * Hc;
        const float* Bbc = ca_qkv_b + (size_t)i * 3 * Hc;
        gemm_kernel<<<g1, 256>>>(h,   Wc,               Bbc,          nullptr, q, Mrows, Hc, Hc, 0);
        gemm_kernel<<<g1, 256>>>(enc, Wc + Hc * Hc,     Bbc + Hc,     nullptr, k, Mrows, Hc, Hc, 0);
        gemm_kernel<<<g1, 256>>>(enc, Wc + 2 * Hc * Hc, Bbc + 2 * Hc, nullptr, v, Mrows, Hc, Hc, 0);
        attn_kernel<<<attnBlocks, 256>>>(q, k, v, emask, a, Sc, Sc);
        gemm_kernel<<<g1, 256>>>(a, ca_out_w + (size_t)i * Hc * Hc, ca_out_b + i * Hc, h, t,
                                 Mrows, Hc, Hc, 0);
        ln_kernel<<<Mrows, 256>>>(t, ca_ln + (size_t)i * 2 * Hc, x2);

        // ---- output_1: x3 = LN(x1 @ o1_w + b + x2) ----
        gemm_kernel<<<g1, 256>>>(x1, o1_w + (size_t)i * Hc * Hc, o1_b + i * Hc, x2, t,
                                 Mrows, Hc, Hc, 0);
        ln_kernel<<<Mrows, 256>>>(t, o1_ln + (size_t)i * 2 * Hc, x3);

        // ---- FFN: inter = gelu(x3 @ ffn_w + b); h = LN(inter @ o2_w + b + x3) ----
        gemm_kernel<<<gF, 256>>>(x3, ffn_w + (size_t)i * Hc * Fc, ffn_b + (size_t)i * Fc,
                                 nullptr, inter, Mrows, Fc, Hc, 1);
        gemm_kernel<<<g1, 256>>>(inter, o2_w + (size_t)i * Fc * Hc, o2_b + i * Hc, x3, t,
                                 Mrows, Hc, Fc, 0);
        ln_kernel<<<Mrows, 256>>>(t, o2_ln + (size_t)i * 2 * Hc,
                                  (i == LAYERS - 1) ? out : h);
    }
}